// round 6
// baseline (speedup 1.0000x reference)
#include <cuda_runtime.h>
#include <cuda_bf16.h>
#include <stdint.h>

#define BATCH 32
#define NPTS  8192
#define NCLST 64
#define C1    128
#define C2    256
#define CF    512
#define CO    384
#define PTOT  (BATCH*NPTS)
#define ENC_NEG_INF 0x007FFFFFu

#define ROWB   80
// stage1 geometry (128x128 tile)
#define PLANE  (128*ROWB)
#define BUFB   (4*PLANE)
// gemm geometry (256 pts x 128 ch tile)
#define APL    (256*ROWB)            // 20480
#define BPL    (128*ROWB)            // 10240
#define BUF64  (2*APL + 2*BPL)       // 61440
#define KC     32

// ---------------- scratch ----------------
__device__ unsigned g_fg[BATCH*NCLST*C2];
__device__ unsigned g_om[BATCH*NCLST*CO];
__device__ __align__(16) uint16_t g_feat_h[(size_t)PTOT*C2];
__device__ __align__(16) uint16_t g_feat_l[(size_t)PTOT*C2];
__device__ __align__(16) uint16_t g_fg_h[BATCH*NCLST*C2];
__device__ __align__(16) uint16_t g_fg_l[BATCH*NCLST*C2];
__device__ __align__(16) uint16_t g_h2_h[(size_t)PTOT*CF];
__device__ __align__(16) uint16_t g_h2_l[(size_t)PTOT*CF];
__device__ __align__(16) uint16_t g_w2_h[C2*C1], g_w2_l[C2*C1];
__device__ __align__(16) uint16_t g_w3_h[CF*CF], g_w3_l[CF*CF];
__device__ __align__(16) uint16_t g_w4_h[CO*CF], g_w4_l[CO*CF];
__device__ float g_s2[CF], g_t2[CF];
__device__ __align__(16) float g_w1f[C1*4];

// ---------------- helpers ----------------
__device__ __forceinline__ unsigned enc(float f){
  unsigned u = __float_as_uint(f);
  return (u & 0x80000000u) ? ~u : (u | 0x80000000u);
}
__device__ __forceinline__ float dec(unsigned u){
  u = (u & 0x80000000u) ? (u & 0x7FFFFFFFu) : ~u;
  return __uint_as_float(u);
}
__device__ __forceinline__ void split2(float v, uint16_t& h, uint16_t& l){
  __nv_bfloat16 bh = __float2bfloat16(v);
  float r = v - __bfloat162float(bh);
  if (!(r == r)) r = 0.f;
  h = __bfloat16_as_ushort(bh);
  l = __bfloat16_as_ushort(__float2bfloat16(r));
}
__device__ __forceinline__ uint32_t smem_u32(const void* p){
  uint32_t a;
  asm("{ .reg .u64 t; cvta.to.shared.u64 t, %1; cvt.u32.u64 %0, t; }" : "=r"(a) : "l"(p));
  return a;
}
__device__ __forceinline__ void cp16(uint32_t dst, const void* src){
  asm volatile("cp.async.cg.shared.global [%0], [%1], 16;" :: "r"(dst), "l"(src));
}
#define CP_COMMIT() asm volatile("cp.async.commit_group;" ::: "memory")
#define CP_WAIT1()  asm volatile("cp.async.wait_group 1;"  ::: "memory")
#define CP_WAIT0()  asm volatile("cp.async.wait_group 0;"  ::: "memory")

__device__ __forceinline__ void ldsm4(uint32_t* r, uint32_t addr){
  asm volatile("ldmatrix.sync.aligned.m8n8.x4.shared.b16 {%0,%1,%2,%3}, [%4];"
    : "=r"(r[0]),"=r"(r[1]),"=r"(r[2]),"=r"(r[3]) : "r"(addr));
}
__device__ __forceinline__ void mma16816(float* c, const uint32_t* a, const uint32_t* b){
  asm volatile("mma.sync.aligned.m16n8k16.row.col.f32.bf16.bf16.f32 "
    "{%0,%1,%2,%3}, {%4,%5,%6,%7}, {%8,%9}, {%0,%1,%2,%3};"
    : "+f"(c[0]),"+f"(c[1]),"+f"(c[2]),"+f"(c[3])
    : "r"(a[0]),"r"(a[1]),"r"(a[2]),"r"(a[3]), "r"(b[0]),"r"(b[1]));
}

// =====================================================================
__global__ void k_init(){
  int i = blockIdx.x*blockDim.x + threadIdx.x;
  if (i < BATCH*NCLST*C2) g_fg[i] = ENC_NEG_INF;
  if (i < BATCH*NCLST*CO) g_om[i] = ENC_NEG_INF;
}

__global__ void k_prep(
    const float* __restrict__ w1, const float* __restrict__ b1,
    const float* __restrict__ bg1, const float* __restrict__ bb1,
    const float* __restrict__ bm1, const float* __restrict__ bv1,
    const float* __restrict__ w2,
    const float* __restrict__ w3, const float* __restrict__ w4,
    const float* __restrict__ b3,
    const float* __restrict__ bg2, const float* __restrict__ bb2,
    const float* __restrict__ bm2, const float* __restrict__ bv2)
{
  int i = blockIdx.x*blockDim.x + threadIdx.x;
  if (i < CF*CF){ uint16_t h,l; split2(w3[i],h,l); g_w3_h[i]=h; g_w3_l[i]=l; }
  int j = i - CF*CF;
  if (j >= 0 && j < CO*CF){ uint16_t h,l; split2(w4[j],h,l); g_w4_h[j]=h; g_w4_l[j]=l; }
  int k = i - CF*CF - CO*CF;
  if (k >= 0 && k < C2*C1){ uint16_t h,l; split2(w2[k],h,l); g_w2_h[k]=h; g_w2_l[k]=l; }
  int m = i - CF*CF - CO*CF - C2*C1;
  if (m >= 0 && m < CF){
    float s = bg2[m] * rsqrtf(bv2[m] + 1e-5f);
    g_s2[m] = s;
    g_t2[m] = bb2[m] + (b3[m] - bm2[m]) * s;
  }
  int q = i - CF*CF - CO*CF - C2*C1 - CF;
  if (q >= 0 && q < C1){
    float s = bg1[q] * rsqrtf(bv1[q] + 1e-5f);
    g_w1f[q*4+0] = w1[q*3+0]*s;
    g_w1f[q*4+1] = w1[q*3+1]*s;
    g_w1f[q*4+2] = w1[q*3+2]*s;
    g_w1f[q*4+3] = (b1[q] - bm1[q])*s + bb1[q];
  }
}

// =====================================================================
// Stage 1 (HMMA, 128x128 tile, 32x32 warp tiles) — round-4 layout
// =====================================================================
struct Frag { float acc[4][4][4]; };

__device__ __forceinline__ void mma_chunk(uint32_t sb, uint32_t aoff, uint32_t boff, Frag& F){
  const uint32_t aAh = sb, aAl = sb + PLANE, aBh = sb + 2*PLANE, aBl = sb + 3*PLANE;
  #pragma unroll
  for (int ks = 0; ks < 2; ks++){
    const uint32_t kb = ks * 32;
    uint32_t a[4][4], bH[2][4], bL[2][4];
    #pragma unroll
    for (int mi=0;mi<4;mi++) ldsm4(a[mi],  aAh + aoff + mi*(16*ROWB) + kb);
    #pragma unroll
    for (int nj=0;nj<2;nj++) ldsm4(bH[nj], aBh + boff + nj*(16*ROWB) + kb);
    #pragma unroll
    for (int mi=0;mi<4;mi++)
      #pragma unroll
      for (int nj=0;nj<2;nj++){
        mma16816(F.acc[mi][nj*2+0], a[mi], &bH[nj][0]);
        mma16816(F.acc[mi][nj*2+1], a[mi], &bH[nj][2]);
      }
    #pragma unroll
    for (int nj=0;nj<2;nj++) ldsm4(bL[nj], aBl + boff + nj*(16*ROWB) + kb);
    #pragma unroll
    for (int mi=0;mi<4;mi++)
      #pragma unroll
      for (int nj=0;nj<2;nj++){
        mma16816(F.acc[mi][nj*2+0], a[mi], &bL[nj][0]);
        mma16816(F.acc[mi][nj*2+1], a[mi], &bL[nj][2]);
      }
    #pragma unroll
    for (int mi=0;mi<4;mi++) ldsm4(a[mi], aAl + aoff + mi*(16*ROWB) + kb);
    #pragma unroll
    for (int mi=0;mi<4;mi++)
      #pragma unroll
      for (int nj=0;nj<2;nj++){
        mma16816(F.acc[mi][nj*2+0], a[mi], &bH[nj][0]);
        mma16816(F.acc[mi][nj*2+1], a[mi], &bH[nj][2]);
      }
  }
}

__global__ __launch_bounds__(256) void k_stage1(
    const float* __restrict__ xyz, const int* __restrict__ choice,
    const float* __restrict__ b2)
{
  extern __shared__ char smem[];
  __shared__ float sx[128][3];
  __shared__ int   scl[128];

  const int t = threadIdx.x, lane = t & 31, wid = t >> 5;
  const int p0 = blockIdx.x*128, bb = blockIdx.x >> 6;
  const int ch0 = blockIdx.y*128;

  for (int i=t; i<128*3; i+=256) sx[i/3][i%3] = xyz[(size_t)p0*3 + i];
  for (int i=t; i<128;   i+=256) scl[i] = choice[p0+i];
  __syncthreads();

  const uint32_t sb = smem_u32(smem);
  uint16_t* pAh = (uint16_t*)smem;
  uint16_t* pAl = (uint16_t*)(smem + PLANE);

  const int wm = (wid & 1)*64, wn = (wid >> 1)*32;
  const uint32_t aoff = (uint32_t)(wm + (lane & 15))*ROWB + ((lane >> 4) & 1)*16;
  const uint32_t boff = (uint32_t)(wn + (lane & 7) + ((lane >> 4) & 1)*8)*ROWB
                      + ((lane >> 3) & 1)*16;

  Frag F;
  #pragma unroll
  for (int mi=0;mi<4;mi++)
    #pragma unroll
    for (int ni=0;ni<4;ni++)
      #pragma unroll
      for (int c=0;c<4;c++) F.acc[mi][ni][c] = 0.f;

  for (int kc=0; kc<4; kc++){
    for (int idx=t; idx<512; idx+=256){
      int row = idx >> 2, c = idx & 3;
      size_t off = (size_t)(ch0+row)*C1 + kc*KC + c*8;
      uint32_t so = (uint32_t)row*ROWB + c*16;
      cp16(sb + 2*PLANE + so, g_w2_h + off);
      cp16(sb + 3*PLANE + so, g_w2_l + off);
    }
    CP_COMMIT();
    for (int idx=t; idx<4096; idx+=256){
      int row = idx >> 5, kp = idx & 31;
      int k = kc*KC + kp;
      float4 wf = *(const float4*)(g_w1f + 4*k);
      float h = fmaf(sx[row][0], wf.x, fmaf(sx[row][1], wf.y, fmaf(sx[row][2], wf.z, wf.w)));
      h = fmaxf(h, 0.f);
      uint16_t hh, hl; split2(h, hh, hl);
      uint32_t so = (uint32_t)row*(ROWB/2) + kp;
      pAh[so] = hh; pAl[so] = hl;
    }
    CP_WAIT0();
    __syncthreads();
    mma_chunk(sb, aoff, boff, F);
    __syncthreads();
  }

  const int r0 = lane >> 2, cp = (lane & 3)*2;
  #pragma unroll
  for (int mi=0;mi<4;mi++){
    int pa = wm + mi*16 + r0;
    size_t ga = (size_t)(p0 + pa), gb = ga + 8;
    unsigned* fra = &g_fg[(size_t)(bb*NCLST + scl[pa])*C2];
    unsigned* frb = &g_fg[(size_t)(bb*NCLST + scl[pa+8])*C2];
    #pragma unroll
    for (int ni=0;ni<4;ni++){
      int ch = ch0 + wn + ni*8 + cp;
      float b0 = b2[ch], b1v = b2[ch+1];
      float x0 = F.acc[mi][ni][0] + b0, x1 = F.acc[mi][ni][1] + b1v;
      float y0 = F.acc[mi][ni][2] + b0, y1 = F.acc[mi][ni][3] + b1v;
      uint16_t h0,l0,h1,l1;
      split2(x0,h0,l0); split2(x1,h1,l1);
      *(uint32_t*)(g_feat_h + ga*C2 + ch) = (uint32_t)h0 | ((uint32_t)h1<<16);
      *(uint32_t*)(g_feat_l + ga*C2 + ch) = (uint32_t)l0 | ((uint32_t)l1<<16);
      atomicMax(&fra[ch],   enc(x0));
      atomicMax(&fra[ch+1], enc(x1));
      split2(y0,h0,l0); split2(y1,h1,l1);
      *(uint32_t*)(g_feat_h + gb*C2 + ch) = (uint32_t)h0 | ((uint32_t)h1<<16);
      *(uint32_t*)(g_feat_l + gb*C2 + ch) = (uint32_t)l0 | ((uint32_t)l1<<16);
      atomicMax(&frb[ch],   enc(y0));
      atomicMax(&frb[ch+1], enc(y1));
    }
  }
}

__global__ void k_fg_split(){
  int i = blockIdx.x*blockDim.x + threadIdx.x;
  if (i < BATCH*NCLST*C2){
    uint16_t h,l; split2(dec(g_fg[i]), h, l);
    g_fg_h[i] = h; g_fg_l[i] = l;
  }
}

// =====================================================================
// 64x64-warp-tile gemm core: CTA = 256 pts x 128 ch, 8 warps (4x2)
// =====================================================================
struct Frag64 { float acc[4][8][4]; };   // 128 floats

__device__ __forceinline__ void mma_chunk64(uint32_t sb, uint32_t aoff, uint32_t boff, Frag64& F){
  const uint32_t aAh = sb, aAl = sb + APL, aBh = sb + 2*APL, aBl = sb + 2*APL + BPL;
  #pragma unroll
  for (int ks = 0; ks < 2; ks++){
    const uint32_t kb = ks * 32;
    uint32_t a[4][4], bH[4][4], bL[4][4];
    #pragma unroll
    for (int mi=0;mi<4;mi++) ldsm4(a[mi],  aAh + aoff + mi*(16*ROWB) + kb);
    #pragma unroll
    for (int nj=0;nj<4;nj++) ldsm4(bH[nj], aBh + boff + nj*(16*ROWB) + kb);
    // term 1: ah * bh
    #pragma unroll
    for (int mi=0;mi<4;mi++)
      #pragma unroll
      for (int nj=0;nj<4;nj++){
        mma16816(F.acc[mi][nj*2+0], a[mi], &bH[nj][0]);
        mma16816(F.acc[mi][nj*2+1], a[mi], &bH[nj][2]);
      }
    // term 2: ah * bl
    #pragma unroll
    for (int nj=0;nj<4;nj++) ldsm4(bL[nj], aBl + boff + nj*(16*ROWB) + kb);
    #pragma unroll
    for (int mi=0;mi<4;mi++)
      #pragma unroll
      for (int nj=0;nj<4;nj++){
        mma16816(F.acc[mi][nj*2+0], a[mi], &bL[nj][0]);
        mma16816(F.acc[mi][nj*2+1], a[mi], &bL[nj][2]);
      }
    // term 3: al * bh
    #pragma unroll
    for (int mi=0;mi<4;mi++) ldsm4(a[mi], aAl + aoff + mi*(16*ROWB) + kb);
    #pragma unroll
    for (int mi=0;mi<4;mi++)
      #pragma unroll
      for (int nj=0;nj<4;nj++){
        mma16816(F.acc[mi][nj*2+0], a[mi], &bH[nj][0]);
        mma16816(F.acc[mi][nj*2+1], a[mi], &bH[nj][2]);
      }
  }
}

template<bool GATHER_A>
__device__ __forceinline__ void gemm_core64(
    uint32_t sb0, const int* scl, int p0, int bb, int ch0,
    const uint16_t* __restrict__ Ah, const uint16_t* __restrict__ Al,
    const uint16_t* __restrict__ Bh, const uint16_t* __restrict__ Bl,
    Frag64& F)
{
  const int t = threadIdx.x, lane = t & 31, wid = t >> 5;
  const int wm = (wid >> 1)*64, wn = (wid & 1)*64;
  const uint32_t aoff = (uint32_t)(wm + (lane & 15))*ROWB + ((lane >> 4) & 1)*16;
  const uint32_t boff = (uint32_t)(wn + (lane & 7) + ((lane >> 4) & 1)*8)*ROWB
                      + ((lane >> 3) & 1)*16;

  #pragma unroll
  for (int mi=0;mi<4;mi++)
    #pragma unroll
    for (int nj=0;nj<8;nj++)
      #pragma unroll
      for (int c=0;c<4;c++) F.acc[mi][nj][c] = 0.f;

  const int NKC = CF / KC;   // 16

  #define ISSUE64(kc) do { \
    uint32_t sbb = sb0 + ((kc)&1)*BUF64; \
    for (int idx=t; idx<1024; idx+=256){ \
      int row = idx >> 2, c = idx & 3; \
      size_t off; \
      const uint16_t *sh, *sl; \
      if (GATHER_A && (kc) < 8){ \
        off = (size_t)(bb*NCLST + scl[row])*C2 + (kc)*KC + c*8; sh = g_fg_h; sl = g_fg_l; \
      } else if (GATHER_A){ \
        off = (size_t)(p0 + row)*C2 + ((kc)-8)*KC + c*8; sh = Ah; sl = Al; \
      } else { \
        off = (size_t)(p0 + row)*CF + (kc)*KC + c*8; sh = Ah; sl = Al; \
      } \
      uint32_t so = (uint32_t)row*ROWB + c*16; \
      cp16(sbb + so,       sh + off); \
      cp16(sbb + APL + so, sl + off); \
    } \
    for (int idx=t; idx<512; idx+=256){ \
      int row = idx >> 2, c = idx & 3; \
      size_t offb = (size_t)(ch0 + row)*CF + (kc)*KC + c*8; \
      uint32_t so = (uint32_t)row*ROWB + c*16; \
      cp16(sbb + 2*APL + so,       Bh + offb); \
      cp16(sbb + 2*APL + BPL + so, Bl + offb); \
    } \
    CP_COMMIT(); \
  } while(0)

  ISSUE64(0);
  for (int kc = 0; kc < NKC; kc++){
    if (kc + 1 < NKC){ ISSUE64(kc+1); CP_WAIT1(); }
    else             { CP_WAIT0(); }
    __syncthreads();
    mma_chunk64(sb0 + (kc&1)*BUF64, aoff, boff, F);
    __syncthreads();
  }
  #undef ISSUE64
}

// GEMM2: h2 = relu(bn2(f @ w3^T + b3)) -> h2 planes. grid (1024, 4)
__global__ __launch_bounds__(256, 1) void k_gemm2(const int* __restrict__ choice)
{
  extern __shared__ char smem[];
  __shared__ int scl[256];
  const int t = threadIdx.x, lane = t & 31, wid = t >> 5;
  const int p0 = blockIdx.x*256, bb = blockIdx.x >> 5;
  const int ch0 = blockIdx.y*128;

  for (int i=t; i<256; i+=256) scl[i] = choice[p0+i];
  __syncthreads();

  Frag64 F;
  gemm_core64<true>(smem_u32(smem), scl, p0, bb, ch0, g_feat_h, g_feat_l, g_w3_h, g_w3_l, F);

  const int wm = (wid >> 1)*64, wn = (wid & 1)*64;
  const int r0 = lane >> 2, cp = (lane & 3)*2;
  #pragma unroll
  for (int mi=0;mi<4;mi++){
    size_t pa = (size_t)(p0 + wm + mi*16 + r0), pb = pa + 8;
    #pragma unroll
    for (int nj=0;nj<8;nj++){
      int ch = ch0 + wn + nj*8 + cp;
      float s0 = g_s2[ch], s1 = g_s2[ch+1];
      float t0 = g_t2[ch], t1 = g_t2[ch+1];
      float x0 = fmaxf(fmaf(F.acc[mi][nj][0], s0, t0), 0.f);
      float x1 = fmaxf(fmaf(F.acc[mi][nj][1], s1, t1), 0.f);
      float y0 = fmaxf(fmaf(F.acc[mi][nj][2], s0, t0), 0.f);
      float y1 = fmaxf(fmaf(F.acc[mi][nj][3], s1, t1), 0.f);
      uint16_t h0,l0,h1,l1;
      split2(x0,h0,l0); split2(x1,h1,l1);
      *(uint32_t*)(g_h2_h + pa*CF + ch) = (uint32_t)h0 | ((uint32_t)h1<<16);
      *(uint32_t*)(g_h2_l + pa*CF + ch) = (uint32_t)l0 | ((uint32_t)l1<<16);
      split2(y0,h0,l0); split2(y1,h1,l1);
      *(uint32_t*)(g_h2_h + pb*CF + ch) = (uint32_t)h0 | ((uint32_t)h1<<16);
      *(uint32_t*)(g_h2_l + pb*CF + ch) = (uint32_t)l0 | ((uint32_t)l1<<16);
    }
  }
}

// GEMM3: out = h2 @ w4^T + b4 -> cluster atomicMax. grid (1024, 3)
__global__ __launch_bounds__(256, 1) void k_gemm3(const int* __restrict__ choice,
                                                  const float* __restrict__ b4)
{
  extern __shared__ char smem[];
  __shared__ int scl[256];
  const int t = threadIdx.x, lane = t & 31, wid = t >> 5;
  const int p0 = blockIdx.x*256, bb = blockIdx.x >> 5;
  const int ch0 = blockIdx.y*128;

  for (int i=t; i<256; i+=256) scl[i] = choice[p0+i];
  __syncthreads();

  Frag64 F;
  gemm_core64<false>(smem_u32(smem), scl, p0, bb, ch0, g_h2_h, g_h2_l, g_w4_h, g_w4_l, F);

  const int wm = (wid >> 1)*64, wn = (wid & 1)*64;
  const int r0 = lane >> 2, cp = (lane & 3)*2;
  #pragma unroll
  for (int mi=0;mi<4;mi++){
    int pa = wm + mi*16 + r0;
    unsigned* ra = &g_om[(size_t)(bb*NCLST + scl[pa])*CO];
    unsigned* rb = &g_om[(size_t)(bb*NCLST + scl[pa+8])*CO];
    #pragma unroll
    for (int nj=0;nj<8;nj++){
      int ch = ch0 + wn + nj*8 + cp;
      float b0 = b4[ch], b1 = b4[ch+1];
      atomicMax(&ra[ch],   enc(F.acc[mi][nj][0] + b0));
      atomicMax(&ra[ch+1], enc(F.acc[mi][nj][1] + b1));
      atomicMax(&rb[ch],   enc(F.acc[mi][nj][2] + b0));
      atomicMax(&rb[ch+1], enc(F.acc[mi][nj][3] + b1));
    }
  }
}

__global__ void k_final(float* __restrict__ out){
  int i = blockIdx.x*blockDim.x + threadIdx.x;
  if (i < BATCH*NCLST*CO) out[i] = dec(g_om[i]);
}

// =====================================================================
extern "C" void kernel_launch(void* const* d_in, const int* in_sizes, int n_in,
                              void* d_out, int out_size)
{
  const float* xyz    = (const float*)d_in[0];
  const int*   choice = (const int*)  d_in[1];
  const float* w1  = (const float*)d_in[2];
  const float* b1  = (const float*)d_in[3];
  const float* g1  = (const float*)d_in[4];
  const float* bb1 = (const float*)d_in[5];
  const float* m1  = (const float*)d_in[6];
  const float* v1  = (const float*)d_in[7];
  const float* w2  = (const float*)d_in[8];
  const float* b2  = (const float*)d_in[9];
  const float* w3  = (const float*)d_in[10];
  const float* b3  = (const float*)d_in[11];
  const float* g2  = (const float*)d_in[12];
  const float* bb2 = (const float*)d_in[13];
  const float* m2  = (const float*)d_in[14];
  const float* v2  = (const float*)d_in[15];
  const float* w4  = (const float*)d_in[16];
  const float* b4  = (const float*)d_in[17];

  size_t smem1 = BUFB;         // 40 KB
  size_t smemg = 2*BUF64;      // 122880 B
  cudaFuncSetAttribute(k_stage1, cudaFuncAttributeMaxDynamicSharedMemorySize, (int)smem1);
  cudaFuncSetAttribute(k_gemm2,  cudaFuncAttributeMaxDynamicSharedMemorySize, (int)smemg);
  cudaFuncSetAttribute(k_gemm3,  cudaFuncAttributeMaxDynamicSharedMemorySize, (int)smemg);

  int ntot  = BATCH*NCLST*CO;
  int nprep = CF*CF + CO*CF + C2*C1 + CF + C1;

  k_init    <<<(ntot+255)/256, 256>>>();
  k_prep    <<<(nprep+255)/256, 256>>>(w1,b1,g1,bb1,m1,v1,w2, w3,w4,b3,g2,bb2,m2,v2);
  {
    dim3 g1d(PTOT/128, C2/128);   // (2048, 2) — round-4 orientation
    k_stage1<<<g1d, 256, smem1>>>(xyz, choice, b2);
  }
  k_fg_split<<<(BATCH*NCLST*C2+255)/256, 256>>>();
  {
    dim3 g2d(PTOT/256, CF/128);   // (1024, 4)
    k_gemm2<<<g2d, 256, smemg>>>(choice);
    dim3 g3d(PTOT/256, CO/128);   // (1024, 3)
    k_gemm3<<<g3d, 256, smemg>>>(choice, b4);
  }
  k_final   <<<(ntot+255)/256, 256>>>((float*)d_out);
}

// round 7
// speedup vs baseline: 1.3222x; 1.3222x over previous
#include <cuda_runtime.h>
#include <cuda_bf16.h>
#include <stdint.h>

#define BATCH 32
#define NPTS  8192
#define NCLST 64
#define C1    128
#define C2    256
#define CF    512
#define CO    384
#define PTOT  (BATCH*NPTS)
#define NFG   (BATCH*NCLST)
#define ENC_NEG_INF 0x007FFFFFu

#define ROWB   80
#define PLANE  (128*ROWB)       // 10240 B
#define BUFB   (4*PLANE)        // 40960 B
#define KC     32

// ---------------- scratch ----------------
__device__ unsigned g_fg[NFG*C2];
__device__ unsigned g_om[NFG*CO];
__device__ __align__(16) uint16_t g_feat_h[(size_t)PTOT*C2];
__device__ __align__(16) uint16_t g_feat_l[(size_t)PTOT*C2];
__device__ __align__(16) uint16_t g_fg_h[NFG*C2];
__device__ __align__(16) uint16_t g_fg_l[NFG*C2];
__device__ __align__(16) uint16_t g_h2_h[(size_t)PTOT*CF];
__device__ __align__(16) uint16_t g_h2_l[(size_t)PTOT*CF];
__device__ __align__(16) uint16_t g_w2_h[C2*C1], g_w2_l[C2*C1];
__device__ __align__(16) uint16_t g_w3_h[CF*CF], g_w3_l[CF*CF];
__device__ __align__(16) uint16_t g_w4_h[CO*CF], g_w4_l[CO*CF];
__device__ float g_G[(size_t)NFG*CF];          // fg @ w3[:, :256]^T  (f32)
__device__ float g_s2[CF], g_t2[CF];
__device__ __align__(16) float g_w1f[C1*4];

// ---------------- helpers ----------------
__device__ __forceinline__ unsigned enc(float f){
  unsigned u = __float_as_uint(f);
  return (u & 0x80000000u) ? ~u : (u | 0x80000000u);
}
__device__ __forceinline__ float dec(unsigned u){
  u = (u & 0x80000000u) ? (u & 0x7FFFFFFFu) : ~u;
  return __uint_as_float(u);
}
__device__ __forceinline__ void split2(float v, uint16_t& h, uint16_t& l){
  __nv_bfloat16 bh = __float2bfloat16(v);
  float r = v - __bfloat162float(bh);
  if (!(r == r)) r = 0.f;
  h = __bfloat16_as_ushort(bh);
  l = __bfloat16_as_ushort(__float2bfloat16(r));
}
__device__ __forceinline__ uint32_t smem_u32(const void* p){
  uint32_t a;
  asm("{ .reg .u64 t; cvta.to.shared.u64 t, %1; cvt.u32.u64 %0, t; }" : "=r"(a) : "l"(p));
  return a;
}
__device__ __forceinline__ void cp16(uint32_t dst, const void* src){
  asm volatile("cp.async.cg.shared.global [%0], [%1], 16;" :: "r"(dst), "l"(src));
}
#define CP_COMMIT() asm volatile("cp.async.commit_group;" ::: "memory")
#define CP_WAIT1()  asm volatile("cp.async.wait_group 1;"  ::: "memory")
#define CP_WAIT0()  asm volatile("cp.async.wait_group 0;"  ::: "memory")

__device__ __forceinline__ void ldsm4(uint32_t* r, uint32_t addr){
  asm volatile("ldmatrix.sync.aligned.m8n8.x4.shared.b16 {%0,%1,%2,%3}, [%4];"
    : "=r"(r[0]),"=r"(r[1]),"=r"(r[2]),"=r"(r[3]) : "r"(addr));
}
__device__ __forceinline__ void mma16816(float* c, const uint32_t* a, const uint32_t* b){
  asm volatile("mma.sync.aligned.m16n8k16.row.col.f32.bf16.bf16.f32 "
    "{%0,%1,%2,%3}, {%4,%5,%6,%7}, {%8,%9}, {%0,%1,%2,%3};"
    : "+f"(c[0]),"+f"(c[1]),"+f"(c[2]),"+f"(c[3])
    : "r"(a[0]),"r"(a[1]),"r"(a[2]),"r"(a[3]), "r"(b[0]),"r"(b[1]));
}

struct Frag { float acc[4][4][4]; };

// 3-term split-bf16 MMA over one staged 32-k buffer (round-4 proven)
__device__ __forceinline__ void mma_chunk(uint32_t sb, uint32_t aoff, uint32_t boff, Frag& F){
  const uint32_t aAh = sb, aAl = sb + PLANE, aBh = sb + 2*PLANE, aBl = sb + 3*PLANE;
  #pragma unroll
  for (int ks = 0; ks < 2; ks++){
    const uint32_t kb = ks * 32;
    uint32_t a[4][4], bH[2][4], bL[2][4];
    #pragma unroll
    for (int mi=0;mi<4;mi++) ldsm4(a[mi],  aAh + aoff + mi*(16*ROWB) + kb);
    #pragma unroll
    for (int nj=0;nj<2;nj++) ldsm4(bH[nj], aBh + boff + nj*(16*ROWB) + kb);
    #pragma unroll
    for (int mi=0;mi<4;mi++)
      #pragma unroll
      for (int nj=0;nj<2;nj++){
        mma16816(F.acc[mi][nj*2+0], a[mi], &bH[nj][0]);
        mma16816(F.acc[mi][nj*2+1], a[mi], &bH[nj][2]);
      }
    #pragma unroll
    for (int nj=0;nj<2;nj++) ldsm4(bL[nj], aBl + boff + nj*(16*ROWB) + kb);
    #pragma unroll
    for (int mi=0;mi<4;mi++)
      #pragma unroll
      for (int nj=0;nj<2;nj++){
        mma16816(F.acc[mi][nj*2+0], a[mi], &bL[nj][0]);
        mma16816(F.acc[mi][nj*2+1], a[mi], &bL[nj][2]);
      }
    #pragma unroll
    for (int mi=0;mi<4;mi++) ldsm4(a[mi], aAl + aoff + mi*(16*ROWB) + kb);
    #pragma unroll
    for (int mi=0;mi<4;mi++)
      #pragma unroll
      for (int nj=0;nj<2;nj++){
        mma16816(F.acc[mi][nj*2+0], a[mi], &bH[nj][0]);
        mma16816(F.acc[mi][nj*2+1], a[mi], &bH[nj][2]);
      }
  }
}

// generic double-buffered 128x128 gemm core (linear A reads)
__device__ __forceinline__ void gemm_core(
    uint32_t sb0, int arow0, const uint16_t* __restrict__ Ah,
    const uint16_t* __restrict__ Al, int astride,
    int ch0, const uint16_t* __restrict__ Bh, const uint16_t* __restrict__ Bl,
    int bkoff, int NKC, Frag& F)
{
  const int t = threadIdx.x, lane = t & 31, wid = t >> 5;
  const int wm = (wid & 1)*64, wn = (wid >> 1)*32;
  const uint32_t aoff = (uint32_t)(wm + (lane & 15))*ROWB + ((lane >> 4) & 1)*16;
  const uint32_t boff = (uint32_t)(wn + (lane & 7) + ((lane >> 4) & 1)*8)*ROWB
                      + ((lane >> 3) & 1)*16;

  #pragma unroll
  for (int mi=0;mi<4;mi++)
    #pragma unroll
    for (int ni=0;ni<4;ni++)
      #pragma unroll
      for (int c=0;c<4;c++) F.acc[mi][ni][c] = 0.f;

  #define ISSUE(kc) do { \
    uint32_t sbb = sb0 + ((kc)&1)*BUFB; \
    for (int idx=t; idx<512; idx+=256){ \
      int row = idx >> 2, c = idx & 3; \
      size_t offa = (size_t)(arow0 + row)*astride + (kc)*KC + c*8; \
      size_t offb = (size_t)(ch0 + row)*CF + bkoff + (kc)*KC + c*8; \
      uint32_t so = (uint32_t)row*ROWB + c*16; \
      cp16(sbb + so,         Ah + offa); \
      cp16(sbb + PLANE + so, Al + offa); \
      cp16(sbb + 2*PLANE + so, Bh + offb); \
      cp16(sbb + 3*PLANE + so, Bl + offb); \
    } \
    CP_COMMIT(); \
  } while(0)

  ISSUE(0);
  for (int kc = 0; kc < NKC; kc++){
    if (kc + 1 < NKC){ ISSUE(kc+1); CP_WAIT1(); }
    else             { CP_WAIT0(); }
    __syncthreads();
    mma_chunk(sb0 + (kc&1)*BUFB, aoff, boff, F);
    __syncthreads();
  }
  #undef ISSUE
}

// =====================================================================
__global__ void k_init(){
  int i = blockIdx.x*blockDim.x + threadIdx.x;
  if (i < NFG*C2) g_fg[i] = ENC_NEG_INF;
  if (i < NFG*CO) g_om[i] = ENC_NEG_INF;
}

__global__ void k_prep(
    const float* __restrict__ w1, const float* __restrict__ b1,
    const float* __restrict__ bg1, const float* __restrict__ bb1,
    const float* __restrict__ bm1, const float* __restrict__ bv1,
    const float* __restrict__ w2,
    const float* __restrict__ w3, const float* __restrict__ w4,
    const float* __restrict__ b3,
    const float* __restrict__ bg2, const float* __restrict__ bb2,
    const float* __restrict__ bm2, const float* __restrict__ bv2)
{
  int i = blockIdx.x*blockDim.x + threadIdx.x;
  if (i < CF*CF){ uint16_t h,l; split2(w3[i],h,l); g_w3_h[i]=h; g_w3_l[i]=l; }
  int j = i - CF*CF;
  if (j >= 0 && j < CO*CF){ uint16_t h,l; split2(w4[j],h,l); g_w4_h[j]=h; g_w4_l[j]=l; }
  int k = i - CF*CF - CO*CF;
  if (k >= 0 && k < C2*C1){ uint16_t h,l; split2(w2[k],h,l); g_w2_h[k]=h; g_w2_l[k]=l; }
  int m = i - CF*CF - CO*CF - C2*C1;
  if (m >= 0 && m < CF){
    float s = bg2[m] * rsqrtf(bv2[m] + 1e-5f);
    g_s2[m] = s;
    g_t2[m] = bb2[m] + (b3[m] - bm2[m]) * s;
  }
  int q = i - CF*CF - CO*CF - C2*C1 - CF;
  if (q >= 0 && q < C1){
    float s = bg1[q] * rsqrtf(bv1[q] + 1e-5f);
    g_w1f[q*4+0] = w1[q*3+0]*s;
    g_w1f[q*4+1] = w1[q*3+1]*s;
    g_w1f[q*4+2] = w1[q*3+2]*s;
    g_w1f[q*4+3] = (b1[q] - bm1[q])*s + bb1[q];
  }
}

// =====================================================================
// Stage 1 (HMMA): feat = relu(bn1(xyz@w1^T+b1)) @ w2^T + b2  (round-4)
// =====================================================================
__global__ __launch_bounds__(256) void k_stage1(
    const float* __restrict__ xyz, const int* __restrict__ choice,
    const float* __restrict__ b2)
{
  extern __shared__ char smem[];
  __shared__ float sx[128][3];
  __shared__ int   scl[128];

  const int t = threadIdx.x, lane = t & 31, wid = t >> 5;
  const int p0 = blockIdx.x*128, bb = blockIdx.x >> 6;
  const int ch0 = blockIdx.y*128;

  for (int i=t; i<128*3; i+=256) sx[i/3][i%3] = xyz[(size_t)p0*3 + i];
  for (int i=t; i<128;   i+=256) scl[i] = choice[p0+i];
  __syncthreads();

  const uint32_t sb = smem_u32(smem);
  uint16_t* pAh = (uint16_t*)smem;
  uint16_t* pAl = (uint16_t*)(smem + PLANE);

  const int wm = (wid & 1)*64, wn = (wid >> 1)*32;
  const uint32_t aoff = (uint32_t)(wm + (lane & 15))*ROWB + ((lane >> 4) & 1)*16;
  const uint32_t boff = (uint32_t)(wn + (lane & 7) + ((lane >> 4) & 1)*8)*ROWB
                      + ((lane >> 3) & 1)*16;

  Frag F;
  #pragma unroll
  for (int mi=0;mi<4;mi++)
    #pragma unroll
    for (int ni=0;ni<4;ni++)
      #pragma unroll
      for (int c=0;c<4;c++) F.acc[mi][ni][c] = 0.f;

  for (int kc=0; kc<4; kc++){
    for (int idx=t; idx<512; idx+=256){
      int row = idx >> 2, c = idx & 3;
      size_t off = (size_t)(ch0+row)*C1 + kc*KC + c*8;
      uint32_t so = (uint32_t)row*ROWB + c*16;
      cp16(sb + 2*PLANE + so, g_w2_h + off);
      cp16(sb + 3*PLANE + so, g_w2_l + off);
    }
    CP_COMMIT();
    for (int idx=t; idx<4096; idx+=256){
      int row = idx >> 5, kp = idx & 31;
      int k = kc*KC + kp;
      float4 wf = *(const float4*)(g_w1f + 4*k);
      float h = fmaf(sx[row][0], wf.x, fmaf(sx[row][1], wf.y, fmaf(sx[row][2], wf.z, wf.w)));
      h = fmaxf(h, 0.f);
      uint16_t hh, hl; split2(h, hh, hl);
      uint32_t so = (uint32_t)row*(ROWB/2) + kp;
      pAh[so] = hh; pAl[so] = hl;
    }
    CP_WAIT0();
    __syncthreads();
    mma_chunk(sb, aoff, boff, F);
    __syncthreads();
  }

  const int r0 = lane >> 2, cp = (lane & 3)*2;
  #pragma unroll
  for (int mi=0;mi<4;mi++){
    int pa = wm + mi*16 + r0;
    size_t ga = (size_t)(p0 + pa), gb = ga + 8;
    unsigned* fra = &g_fg[(size_t)(bb*NCLST + scl[pa])*C2];
    unsigned* frb = &g_fg[(size_t)(bb*NCLST + scl[pa+8])*C2];
    #pragma unroll
    for (int ni=0;ni<4;ni++){
      int ch = ch0 + wn + ni*8 + cp;
      float b0 = b2[ch], b1v = b2[ch+1];
      float x0 = F.acc[mi][ni][0] + b0, x1 = F.acc[mi][ni][1] + b1v;
      float y0 = F.acc[mi][ni][2] + b0, y1 = F.acc[mi][ni][3] + b1v;
      uint16_t h0,l0,h1,l1;
      split2(x0,h0,l0); split2(x1,h1,l1);
      *(uint32_t*)(g_feat_h + ga*C2 + ch) = (uint32_t)h0 | ((uint32_t)h1<<16);
      *(uint32_t*)(g_feat_l + ga*C2 + ch) = (uint32_t)l0 | ((uint32_t)l1<<16);
      atomicMax(&fra[ch],   enc(x0));
      atomicMax(&fra[ch+1], enc(x1));
      split2(y0,h0,l0); split2(y1,h1,l1);
      *(uint32_t*)(g_feat_h + gb*C2 + ch) = (uint32_t)h0 | ((uint32_t)h1<<16);
      *(uint32_t*)(g_feat_l + gb*C2 + ch) = (uint32_t)l0 | ((uint32_t)l1<<16);
      atomicMax(&frb[ch],   enc(y0));
      atomicMax(&frb[ch+1], enc(y1));
    }
  }
}

__global__ void k_fg_split(){
  int i = blockIdx.x*blockDim.x + threadIdx.x;
  if (i < NFG*C2){
    uint16_t h,l; split2(dec(g_fg[i]), h, l);
    g_fg_h[i] = h; g_fg_l[i] = l;
  }
}

// =====================================================================
// Cluster GEMM: G[2048][512] = fg @ w3[:, :256]^T   (K=256, tiny)
// grid (16, 4)
// =====================================================================
__global__ __launch_bounds__(256) void k_gemmC()
{
  extern __shared__ char smem[];
  const int t = threadIdx.x, lane = t & 31, wid = t >> 5;
  const int r0b = blockIdx.x*128;
  const int ch0 = blockIdx.y*128;

  Frag F;
  gemm_core(smem_u32(smem), r0b, g_fg_h, g_fg_l, C2, ch0, g_w3_h, g_w3_l, 0, C2/KC, F);

  const int wm = (wid & 1)*64, wn = (wid >> 1)*32;
  const int r0 = lane >> 2, cp = (lane & 3)*2;
  #pragma unroll
  for (int mi=0;mi<4;mi++){
    size_t ga = (size_t)(r0b + wm + mi*16 + r0), gb = ga + 8;
    #pragma unroll
    for (int ni=0;ni<4;ni++){
      int ch = ch0 + wn + ni*8 + cp;
      *(float2*)(g_G + ga*CF + ch) = make_float2(F.acc[mi][ni][0], F.acc[mi][ni][1]);
      *(float2*)(g_G + gb*CF + ch) = make_float2(F.acc[mi][ni][2], F.acc[mi][ni][3]);
    }
  }
}

// =====================================================================
// GEMM2 (K=256 now): h2 = relu(bn2(feat @ w3[:,256:]^T + G[cluster] ))
// grid (2048, 4)
// =====================================================================
__global__ __launch_bounds__(256) void k_gemm2(const int* __restrict__ choice)
{
  extern __shared__ char smem[];
  __shared__ int scl[128];
  const int t = threadIdx.x, lane = t & 31, wid = t >> 5;
  const int p0 = blockIdx.x*128, bb = blockIdx.x >> 6;
  const int ch0 = blockIdx.y*128;

  for (int i=t; i<128; i+=256) scl[i] = choice[p0+i];
  __syncthreads();

  Frag F;
  gemm_core(smem_u32(smem), p0, g_feat_h, g_feat_l, C2, ch0, g_w3_h, g_w3_l, C2, C2/KC, F);

  const int wm = (wid & 1)*64, wn = (wid >> 1)*32;
  const int r0 = lane >> 2, cp = (lane & 3)*2;
  #pragma unroll
  for (int mi=0;mi<4;mi++){
    int pa = wm + mi*16 + r0;
    size_t ga = (size_t)(p0 + pa), gb = ga + 8;
    const float* Ga = &g_G[(size_t)(bb*NCLST + scl[pa])*CF];
    const float* Gb = &g_G[(size_t)(bb*NCLST + scl[pa+8])*CF];
    #pragma unroll
    for (int ni=0;ni<4;ni++){
      int ch = ch0 + wn + ni*8 + cp;
      float s0 = g_s2[ch], s1 = g_s2[ch+1];
      float t0 = g_t2[ch], t1 = g_t2[ch+1];
      float2 gva = *(const float2*)(Ga + ch);
      float2 gvb = *(const float2*)(Gb + ch);
      float x0 = fmaxf(fmaf(F.acc[mi][ni][0] + gva.x, s0, t0), 0.f);
      float x1 = fmaxf(fmaf(F.acc[mi][ni][1] + gva.y, s1, t1), 0.f);
      float y0 = fmaxf(fmaf(F.acc[mi][ni][2] + gvb.x, s0, t0), 0.f);
      float y1 = fmaxf(fmaf(F.acc[mi][ni][3] + gvb.y, s1, t1), 0.f);
      uint16_t h0,l0,h1,l1;
      split2(x0,h0,l0); split2(x1,h1,l1);
      *(uint32_t*)(g_h2_h + ga*CF + ch) = (uint32_t)h0 | ((uint32_t)h1<<16);
      *(uint32_t*)(g_h2_l + ga*CF + ch) = (uint32_t)l0 | ((uint32_t)l1<<16);
      split2(y0,h0,l0); split2(y1,h1,l1);
      *(uint32_t*)(g_h2_h + gb*CF + ch) = (uint32_t)h0 | ((uint32_t)h1<<16);
      *(uint32_t*)(g_h2_l + gb*CF + ch) = (uint32_t)l0 | ((uint32_t)l1<<16);
    }
  }
}

// =====================================================================
// GEMM3: out = h2 @ w4^T + b4 -> cluster atomicMax.  grid (2048, 3)
// =====================================================================
__global__ __launch_bounds__(256) void k_gemm3(const int* __restrict__ choice,
                                               const float* __restrict__ b4)
{
  extern __shared__ char smem[];
  __shared__ int scl[128];
  const int t = threadIdx.x, lane = t & 31, wid = t >> 5;
  const int p0 = blockIdx.x*128, bb = blockIdx.x >> 6;
  const int ch0 = blockIdx.y*128;

  for (int i=t; i<128; i+=256) scl[i] = choice[p0+i];
  __syncthreads();

  Frag F;
  gemm_core(smem_u32(smem), p0, g_h2_h, g_h2_l, CF, ch0, g_w4_h, g_w4_l, 0, CF/KC, F);

  const int wm = (wid & 1)*64, wn = (wid >> 1)*32;
  const int r0 = lane >> 2, cp = (lane & 3)*2;
  #pragma unroll
  for (int mi=0;mi<4;mi++){
    int pa = wm + mi*16 + r0;
    unsigned* ra = &g_om[(size_t)(bb*NCLST + scl[pa])*CO];
    unsigned* rb = &g_om[(size_t)(bb*NCLST + scl[pa+8])*CO];
    #pragma unroll
    for (int ni=0;ni<4;ni++){
      int ch = ch0 + wn + ni*8 + cp;
      float b0 = b4[ch], b1 = b4[ch+1];
      atomicMax(&ra[ch],   enc(F.acc[mi][ni][0] + b0));
      atomicMax(&ra[ch+1], enc(F.acc[mi][ni][1] + b1));
      atomicMax(&rb[ch],   enc(F.acc[mi][ni][2] + b0));
      atomicMax(&rb[ch+1], enc(F.acc[mi][ni][3] + b1));
    }
  }
}

__global__ void k_final(float* __restrict__ out){
  int i = blockIdx.x*blockDim.x + threadIdx.x;
  if (i < NFG*CO) out[i] = dec(g_om[i]);
}

// =====================================================================
extern "C" void kernel_launch(void* const* d_in, const int* in_sizes, int n_in,
                              void* d_out, int out_size)
{
  const float* xyz    = (const float*)d_in[0];
  const int*   choice = (const int*)  d_in[1];
  const float* w1  = (const float*)d_in[2];
  const float* b1  = (const float*)d_in[3];
  const float* g1  = (const float*)d_in[4];
  const float* bb1 = (const float*)d_in[5];
  const float* m1  = (const float*)d_in[6];
  const float* v1  = (const float*)d_in[7];
  const float* w2  = (const float*)d_in[8];
  const float* b2  = (const float*)d_in[9];
  const float* w3  = (const float*)d_in[10];
  const float* b3  = (const float*)d_in[11];
  const float* g2  = (const float*)d_in[12];
  const float* bb2 = (const float*)d_in[13];
  const float* m2  = (const float*)d_in[14];
  const float* v2  = (const float*)d_in[15];
  const float* w4  = (const float*)d_in[16];
  const float* b4  = (const float*)d_in[17];

  size_t smem1 = BUFB;       // 40 KB
  size_t smemg = 2*BUFB;     // 80 KB
  cudaFuncSetAttribute(k_stage1, cudaFuncAttributeMaxDynamicSharedMemorySize, (int)smem1);
  cudaFuncSetAttribute(k_gemmC,  cudaFuncAttributeMaxDynamicSharedMemorySize, (int)smemg);
  cudaFuncSetAttribute(k_gemm2,  cudaFuncAttributeMaxDynamicSharedMemorySize, (int)smemg);
  cudaFuncSetAttribute(k_gemm3,  cudaFuncAttributeMaxDynamicSharedMemorySize, (int)smemg);

  int ntot  = NFG*CO;
  int nprep = CF*CF + CO*CF + C2*C1 + CF + C1;

  k_init    <<<(ntot+255)/256, 256>>>();
  k_prep    <<<(nprep+255)/256, 256>>>(w1,b1,g1,bb1,m1,v1,w2, w3,w4,b3,g2,bb2,m2,v2);
  {
    dim3 g1d(PTOT/128, C2/128);   // (2048, 2)
    k_stage1<<<g1d, 256, smem1>>>(xyz, choice, b2);
  }
  k_fg_split<<<(NFG*C2+255)/256, 256>>>();
  {
    dim3 gcd(NFG/128, CF/128);    // (16, 4)
    k_gemmC<<<gcd, 256, smemg>>>();
    dim3 g2d(PTOT/128, CF/128);   // (2048, 4)
    k_gemm2<<<g2d, 256, smemg>>>(choice);
    dim3 g3d(PTOT/128, CO/128);   // (2048, 3)
    k_gemm3<<<g3d, 256, smemg>>>(choice, b4);
  }
  k_final   <<<(ntot+255)/256, 256>>>((float*)d_out);
}

// round 8
// speedup vs baseline: 1.3865x; 1.0487x over previous
#include <cuda_runtime.h>
#include <cuda_bf16.h>
#include <stdint.h>

#define BATCH 32
#define NPTS  8192
#define NCLST 64
#define C1    128
#define C2    256
#define CF    512
#define CO    384
#define PTOT  (BATCH*NPTS)
#define NFG   (BATCH*NCLST)
#define ENC_NEG_INF 0x007FFFFFu

#define ROWB   80
#define PLANE  (128*ROWB)       // 10240 B
#define BUFB   (4*PLANE)        // 40960 B
#define KC     32
#define SVSTR  130              // f32 stride of epilogue tile
#define SVB    (128*SVSTR*4)    // 66560 B

// ---------------- scratch ----------------
__device__ unsigned g_fg[NFG*C2];
__device__ unsigned g_om[NFG*CO];
__device__ int g_perm[PTOT];                   // sorted pos -> original idx
__device__ int g_chs[PTOT];                    // cluster id at sorted pos
__device__ __align__(16) uint16_t g_feat_h[(size_t)PTOT*C2];
__device__ __align__(16) uint16_t g_feat_l[(size_t)PTOT*C2];
__device__ __align__(16) uint16_t g_fg_h[NFG*C2];
__device__ __align__(16) uint16_t g_fg_l[NFG*C2];
__device__ __align__(16) uint16_t g_h2_h[(size_t)PTOT*CF];
__device__ __align__(16) uint16_t g_h2_l[(size_t)PTOT*CF];
__device__ __align__(16) uint16_t g_w2_h[C2*C1], g_w2_l[C2*C1];
__device__ __align__(16) uint16_t g_w3_h[CF*CF], g_w3_l[CF*CF];
__device__ __align__(16) uint16_t g_w4_h[CO*CF], g_w4_l[CO*CF];
__device__ float g_G[(size_t)NFG*CF];
__device__ float g_s2[CF], g_t2[CF];
__device__ __align__(16) float g_w1f[C1*4];

// ---------------- helpers ----------------
__device__ __forceinline__ unsigned enc(float f){
  unsigned u = __float_as_uint(f);
  return (u & 0x80000000u) ? ~u : (u | 0x80000000u);
}
__device__ __forceinline__ float dec(unsigned u){
  u = (u & 0x80000000u) ? (u & 0x7FFFFFFFu) : ~u;
  return __uint_as_float(u);
}
__device__ __forceinline__ void split2(float v, uint16_t& h, uint16_t& l){
  __nv_bfloat16 bh = __float2bfloat16(v);
  float r = v - __bfloat162float(bh);
  if (!(r == r)) r = 0.f;
  h = __bfloat16_as_ushort(bh);
  l = __bfloat16_as_ushort(__float2bfloat16(r));
}
__device__ __forceinline__ uint32_t smem_u32(const void* p){
  uint32_t a;
  asm("{ .reg .u64 t; cvta.to.shared.u64 t, %1; cvt.u32.u64 %0, t; }" : "=r"(a) : "l"(p));
  return a;
}
__device__ __forceinline__ void cp16(uint32_t dst, const void* src){
  asm volatile("cp.async.cg.shared.global [%0], [%1], 16;" :: "r"(dst), "l"(src));
}
#define CP_COMMIT() asm volatile("cp.async.commit_group;" ::: "memory")
#define CP_WAIT1()  asm volatile("cp.async.wait_group 1;"  ::: "memory")
#define CP_WAIT0()  asm volatile("cp.async.wait_group 0;"  ::: "memory")

__device__ __forceinline__ void ldsm4(uint32_t* r, uint32_t addr){
  asm volatile("ldmatrix.sync.aligned.m8n8.x4.shared.b16 {%0,%1,%2,%3}, [%4];"
    : "=r"(r[0]),"=r"(r[1]),"=r"(r[2]),"=r"(r[3]) : "r"(addr));
}
__device__ __forceinline__ void mma16816(float* c, const uint32_t* a, const uint32_t* b){
  asm volatile("mma.sync.aligned.m16n8k16.row.col.f32.bf16.bf16.f32 "
    "{%0,%1,%2,%3}, {%4,%5,%6,%7}, {%8,%9}, {%0,%1,%2,%3};"
    : "+f"(c[0]),"+f"(c[1]),"+f"(c[2]),"+f"(c[3])
    : "r"(a[0]),"r"(a[1]),"r"(a[2]),"r"(a[3]), "r"(b[0]),"r"(b[1]));
}

struct Frag { float acc[4][4][4]; };

__device__ __forceinline__ void mma_chunk(uint32_t sb, uint32_t aoff, uint32_t boff, Frag& F){
  const uint32_t aAh = sb, aAl = sb + PLANE, aBh = sb + 2*PLANE, aBl = sb + 3*PLANE;
  #pragma unroll
  for (int ks = 0; ks < 2; ks++){
    const uint32_t kb = ks * 32;
    uint32_t a[4][4], bH[2][4], bL[2][4];
    #pragma unroll
    for (int mi=0;mi<4;mi++) ldsm4(a[mi],  aAh + aoff + mi*(16*ROWB) + kb);
    #pragma unroll
    for (int nj=0;nj<2;nj++) ldsm4(bH[nj], aBh + boff + nj*(16*ROWB) + kb);
    #pragma unroll
    for (int mi=0;mi<4;mi++)
      #pragma unroll
      for (int nj=0;nj<2;nj++){
        mma16816(F.acc[mi][nj*2+0], a[mi], &bH[nj][0]);
        mma16816(F.acc[mi][nj*2+1], a[mi], &bH[nj][2]);
      }
    #pragma unroll
    for (int nj=0;nj<2;nj++) ldsm4(bL[nj], aBl + boff + nj*(16*ROWB) + kb);
    #pragma unroll
    for (int mi=0;mi<4;mi++)
      #pragma unroll
      for (int nj=0;nj<2;nj++){
        mma16816(F.acc[mi][nj*2+0], a[mi], &bL[nj][0]);
        mma16816(F.acc[mi][nj*2+1], a[mi], &bL[nj][2]);
      }
    #pragma unroll
    for (int mi=0;mi<4;mi++) ldsm4(a[mi], aAl + aoff + mi*(16*ROWB) + kb);
    #pragma unroll
    for (int mi=0;mi<4;mi++)
      #pragma unroll
      for (int nj=0;nj<2;nj++){
        mma16816(F.acc[mi][nj*2+0], a[mi], &bH[nj][0]);
        mma16816(F.acc[mi][nj*2+1], a[mi], &bH[nj][2]);
      }
  }
}

__device__ __forceinline__ void gemm_core(
    uint32_t sb0, int arow0, const uint16_t* __restrict__ Ah,
    const uint16_t* __restrict__ Al, int astride,
    int ch0, const uint16_t* __restrict__ Bh, const uint16_t* __restrict__ Bl,
    int bkoff, int NKC, Frag& F)
{
  const int t = threadIdx.x, lane = t & 31, wid = t >> 5;
  const int wm = (wid & 1)*64, wn = (wid >> 1)*32;
  const uint32_t aoff = (uint32_t)(wm + (lane & 15))*ROWB + ((lane >> 4) & 1)*16;
  const uint32_t boff = (uint32_t)(wn + (lane & 7) + ((lane >> 4) & 1)*8)*ROWB
                      + ((lane >> 3) & 1)*16;

  #pragma unroll
  for (int mi=0;mi<4;mi++)
    #pragma unroll
    for (int ni=0;ni<4;ni++)
      #pragma unroll
      for (int c=0;c<4;c++) F.acc[mi][ni][c] = 0.f;

  #define ISSUE(kc) do { \
    uint32_t sbb = sb0 + ((kc)&1)*BUFB; \
    for (int idx=t; idx<512; idx+=256){ \
      int row = idx >> 2, c = idx & 3; \
      size_t offa = (size_t)(arow0 + row)*astride + (kc)*KC + c*8; \
      size_t offb = (size_t)(ch0 + row)*CF + bkoff + (kc)*KC + c*8; \
      uint32_t so = (uint32_t)row*ROWB + c*16; \
      cp16(sbb + so,         Ah + offa); \
      cp16(sbb + PLANE + so, Al + offa); \
      cp16(sbb + 2*PLANE + so, Bh + offb); \
      cp16(sbb + 3*PLANE + so, Bl + offb); \
    } \
    CP_COMMIT(); \
  } while(0)

  ISSUE(0);
  for (int kc = 0; kc < NKC; kc++){
    if (kc + 1 < NKC){ ISSUE(kc+1); CP_WAIT1(); }
    else             { CP_WAIT0(); }
    __syncthreads();
    mma_chunk(sb0 + (kc&1)*BUFB, aoff, boff, F);
    __syncthreads();
  }
  #undef ISSUE
}

// =====================================================================
__global__ void k_init(){
  int i = blockIdx.x*blockDim.x + threadIdx.x;
  if (i < NFG*C2) g_fg[i] = ENC_NEG_INF;
  if (i < NFG*CO) g_om[i] = ENC_NEG_INF;
}

// counting sort per batch: 1 CTA / batch
__global__ __launch_bounds__(256) void k_sort(const int* __restrict__ choice){
  __shared__ int offs[NCLST];
  __shared__ int hist[NCLST];
  const int t = threadIdx.x, b = blockIdx.x;
  const int base = b*NPTS;
  if (t < NCLST){ hist[t] = 0; }
  __syncthreads();
  for (int i=t; i<NPTS; i+=256) atomicAdd(&hist[choice[base+i]], 1);
  __syncthreads();
  if (t == 0){
    int s = 0;
    for (int c=0;c<NCLST;c++){ offs[c] = s; s += hist[c]; }
  }
  __syncthreads();
  for (int i=t; i<NPTS; i+=256){
    int c = choice[base+i];
    int pos = atomicAdd(&offs[c], 1);
    g_perm[base+pos] = base + i;
    g_chs [base+pos] = c;
  }
}

__global__ void k_prep(
    const float* __restrict__ w1, const float* __restrict__ b1,
    const float* __restrict__ bg1, const float* __restrict__ bb1,
    const float* __restrict__ bm1, const float* __restrict__ bv1,
    const float* __restrict__ w2,
    const float* __restrict__ w3, const float* __restrict__ w4,
    const float* __restrict__ b3,
    const float* __restrict__ bg2, const float* __restrict__ bb2,
    const float* __restrict__ bm2, const float* __restrict__ bv2)
{
  int i = blockIdx.x*blockDim.x + threadIdx.x;
  if (i < CF*CF){ uint16_t h,l; split2(w3[i],h,l); g_w3_h[i]=h; g_w3_l[i]=l; }
  int j = i - CF*CF;
  if (j >= 0 && j < CO*CF){ uint16_t h,l; split2(w4[j],h,l); g_w4_h[j]=h; g_w4_l[j]=l; }
  int k = i - CF*CF - CO*CF;
  if (k >= 0 && k < C2*C1){ uint16_t h,l; split2(w2[k],h,l); g_w2_h[k]=h; g_w2_l[k]=l; }
  int m = i - CF*CF - CO*CF - C2*C1;
  if (m >= 0 && m < CF){
    float s = bg2[m] * rsqrtf(bv2[m] + 1e-5f);
    g_s2[m] = s;
    g_t2[m] = bb2[m] + (b3[m] - bm2[m]) * s;
  }
  int q = i - CF*CF - CO*CF - C2*C1 - CF;
  if (q >= 0 && q < C1){
    float s = bg1[q] * rsqrtf(bv1[q] + 1e-5f);
    g_w1f[q*4+0] = w1[q*3+0]*s;
    g_w1f[q*4+1] = w1[q*3+1]*s;
    g_w1f[q*4+2] = w1[q*3+2]*s;
    g_w1f[q*4+3] = (b1[q] - bm1[q])*s + bb1[q];
  }
}

// =====================================================================
// Stage 1 (HMMA, sorted points): feat_sorted + segment-reduced fg max
// =====================================================================
__global__ __launch_bounds__(256) void k_stage1(
    const float* __restrict__ xyz, const float* __restrict__ b2)
{
  extern __shared__ char smem[];
  __shared__ float sx[128][3];
  __shared__ int   scl[128];
  __shared__ int   sperm[128];

  const int t = threadIdx.x, lane = t & 31, wid = t >> 5;
  const int p0 = blockIdx.x*128, bb = blockIdx.x >> 6;
  const int ch0 = blockIdx.y*128;

  for (int i=t; i<128; i+=256){ scl[i] = g_chs[p0+i]; sperm[i] = g_perm[p0+i]; }
  __syncthreads();
  for (int i=t; i<128*3; i+=256) sx[i/3][i%3] = xyz[(size_t)sperm[i/3]*3 + (i%3)];
  __syncthreads();

  const uint32_t sb = smem_u32(smem);
  uint16_t* pAh = (uint16_t*)smem;
  uint16_t* pAl = (uint16_t*)(smem + PLANE);

  const int wm = (wid & 1)*64, wn = (wid >> 1)*32;
  const uint32_t aoff = (uint32_t)(wm + (lane & 15))*ROWB + ((lane >> 4) & 1)*16;
  const uint32_t boff = (uint32_t)(wn + (lane & 7) + ((lane >> 4) & 1)*8)*ROWB
                      + ((lane >> 3) & 1)*16;

  Frag F;
  #pragma unroll
  for (int mi=0;mi<4;mi++)
    #pragma unroll
    for (int ni=0;ni<4;ni++)
      #pragma unroll
      for (int c=0;c<4;c++) F.acc[mi][ni][c] = 0.f;

  for (int kc=0; kc<4; kc++){
    for (int idx=t; idx<512; idx+=256){
      int row = idx >> 2, c = idx & 3;
      size_t off = (size_t)(ch0+row)*C1 + kc*KC + c*8;
      uint32_t so = (uint32_t)row*ROWB + c*16;
      cp16(sb + 2*PLANE + so, g_w2_h + off);
      cp16(sb + 3*PLANE + so, g_w2_l + off);
    }
    CP_COMMIT();
    for (int idx=t; idx<4096; idx+=256){
      int row = idx >> 5, kp = idx & 31;
      int k = kc*KC + kp;
      float4 wf = *(const float4*)(g_w1f + 4*k);
      float h = fmaf(sx[row][0], wf.x, fmaf(sx[row][1], wf.y, fmaf(sx[row][2], wf.z, wf.w)));
      h = fmaxf(h, 0.f);
      uint16_t hh, hl; split2(h, hh, hl);
      uint32_t so = (uint32_t)row*(ROWB/2) + kp;
      pAh[so] = hh; pAl[so] = hl;
    }
    CP_WAIT0();
    __syncthreads();
    mma_chunk(sb, aoff, boff, F);
    __syncthreads();
  }

  // epilogue: write feat (sorted layout) + stage tile in smem
  float* Sv = (float*)smem;       // [128][SVSTR] f32, reuse staging
  const int r0 = lane >> 2, cp = (lane & 3)*2;
  #pragma unroll
  for (int mi=0;mi<4;mi++){
    int pa = wm + mi*16 + r0;
    size_t ga = (size_t)(p0 + pa), gb = ga + 8;
    #pragma unroll
    for (int ni=0;ni<4;ni++){
      int chl = wn + ni*8 + cp;
      int ch  = ch0 + chl;
      float b0 = b2[ch], b1v = b2[ch+1];
      float x0 = F.acc[mi][ni][0] + b0, x1 = F.acc[mi][ni][1] + b1v;
      float y0 = F.acc[mi][ni][2] + b0, y1 = F.acc[mi][ni][3] + b1v;
      uint16_t h0,l0,h1,l1;
      split2(x0,h0,l0); split2(x1,h1,l1);
      *(uint32_t*)(g_feat_h + ga*C2 + ch) = (uint32_t)h0 | ((uint32_t)h1<<16);
      *(uint32_t*)(g_feat_l + ga*C2 + ch) = (uint32_t)l0 | ((uint32_t)l1<<16);
      split2(y0,h0,l0); split2(y1,h1,l1);
      *(uint32_t*)(g_feat_h + gb*C2 + ch) = (uint32_t)h0 | ((uint32_t)h1<<16);
      *(uint32_t*)(g_feat_l + gb*C2 + ch) = (uint32_t)l0 | ((uint32_t)l1<<16);
      *(float2*)&Sv[(size_t)pa*SVSTR + chl]     = make_float2(x0, x1);
      *(float2*)&Sv[(size_t)(pa+8)*SVSTR + chl] = make_float2(y0, y1);
    }
  }
  __syncthreads();

  // segment-reduced cluster max: 2 threads per channel walk 64 sorted rows
  {
    const int ch = t & 127, half = t >> 7;
    int r = half*64;
    int cprev = scl[r];
    float run = __int_as_float(0xff800000);
    unsigned* fgb = &g_fg[(size_t)bb*NCLST*C2 + ch0 + ch];
    for (int i=0;i<64;i++,r++){
      int c = scl[r];
      if (c != cprev){
        atomicMax(&fgb[(size_t)cprev*C2], enc(run));
        run = __int_as_float(0xff800000);
        cprev = c;
      }
      run = fmaxf(run, Sv[(size_t)r*SVSTR + ch]);
    }
    atomicMax(&fgb[(size_t)cprev*C2], enc(run));
  }
}

__global__ void k_fg_split(){
  int i = blockIdx.x*blockDim.x + threadIdx.x;
  if (i < NFG*C2){
    uint16_t h,l; split2(dec(g_fg[i]), h, l);
    g_fg_h[i] = h; g_fg_l[i] = l;
  }
}

// =====================================================================
// Cluster GEMM: G = fg @ w3[:, :256]^T   grid (16, 4)
// =====================================================================
__global__ __launch_bounds__(256) void k_gemmC()
{
  extern __shared__ char smem[];
  const int t = threadIdx.x, lane = t & 31, wid = t >> 5;
  const int r0b = blockIdx.x*128;
  const int ch0 = blockIdx.y*128;

  Frag F;
  gemm_core(smem_u32(smem), r0b, g_fg_h, g_fg_l, C2, ch0, g_w3_h, g_w3_l, 0, C2/KC, F);

  const int wm = (wid & 1)*64, wn = (wid >> 1)*32;
  const int r0 = lane >> 2, cp = (lane & 3)*2;
  #pragma unroll
  for (int mi=0;mi<4;mi++){
    size_t ga = (size_t)(r0b + wm + mi*16 + r0), gb = ga + 8;
    #pragma unroll
    for (int ni=0;ni<4;ni++){
      int ch = ch0 + wn + ni*8 + cp;
      *(float2*)(g_G + ga*CF + ch) = make_float2(F.acc[mi][ni][0], F.acc[mi][ni][1]);
      *(float2*)(g_G + gb*CF + ch) = make_float2(F.acc[mi][ni][2], F.acc[mi][ni][3]);
    }
  }
}

// =====================================================================
// GEMM2 (K=256): h2 = relu(bn2(feat @ w3[:,256:]^T + G[cluster]))
// =====================================================================
__global__ __launch_bounds__(256) void k_gemm2()
{
  extern __shared__ char smem[];
  __shared__ int scl[128];
  const int t = threadIdx.x, lane = t & 31, wid = t >> 5;
  const int p0 = blockIdx.x*128, bb = blockIdx.x >> 6;
  const int ch0 = blockIdx.y*128;

  for (int i=t; i<128; i+=256) scl[i] = g_chs[p0+i];
  __syncthreads();

  Frag F;
  gemm_core(smem_u32(smem), p0, g_feat_h, g_feat_l, C2, ch0, g_w3_h, g_w3_l, C2, C2/KC, F);

  const int wm = (wid & 1)*64, wn = (wid >> 1)*32;
  const int r0 = lane >> 2, cp = (lane & 3)*2;
  #pragma unroll
  for (int mi=0;mi<4;mi++){
    int pa = wm + mi*16 + r0;
    size_t ga = (size_t)(p0 + pa), gb = ga + 8;
    const float* Ga = &g_G[(size_t)(bb*NCLST + scl[pa])*CF];
    const float* Gb = &g_G[(size_t)(bb*NCLST + scl[pa+8])*CF];
    #pragma unroll
    for (int ni=0;ni<4;ni++){
      int ch = ch0 + wn + ni*8 + cp;
      float s0 = g_s2[ch], s1 = g_s2[ch+1];
      float t0 = g_t2[ch], t1 = g_t2[ch+1];
      float2 gva = *(const float2*)(Ga + ch);
      float2 gvb = *(const float2*)(Gb + ch);
      float x0 = fmaxf(fmaf(F.acc[mi][ni][0] + gva.x, s0, t0), 0.f);
      float x1 = fmaxf(fmaf(F.acc[mi][ni][1] + gva.y, s1, t1), 0.f);
      float y0 = fmaxf(fmaf(F.acc[mi][ni][2] + gvb.x, s0, t0), 0.f);
      float y1 = fmaxf(fmaf(F.acc[mi][ni][3] + gvb.y, s1, t1), 0.f);
      uint16_t h0,l0,h1,l1;
      split2(x0,h0,l0); split2(x1,h1,l1);
      *(uint32_t*)(g_h2_h + ga*CF + ch) = (uint32_t)h0 | ((uint32_t)h1<<16);
      *(uint32_t*)(g_h2_l + ga*CF + ch) = (uint32_t)l0 | ((uint32_t)l1<<16);
      split2(y0,h0,l0); split2(y1,h1,l1);
      *(uint32_t*)(g_h2_h + gb*CF + ch) = (uint32_t)h0 | ((uint32_t)h1<<16);
      *(uint32_t*)(g_h2_l + gb*CF + ch) = (uint32_t)l0 | ((uint32_t)l1<<16);
    }
  }
}

// =====================================================================
// GEMM3: out = h2 @ w4^T + b4 -> segment-reduced cluster max
// =====================================================================
__global__ __launch_bounds__(256) void k_gemm3(const float* __restrict__ b4)
{
  extern __shared__ char smem[];
  __shared__ int scl[128];
  const int t = threadIdx.x, lane = t & 31, wid = t >> 5;
  const int p0 = blockIdx.x*128, bb = blockIdx.x >> 6;
  const int ch0 = blockIdx.y*128;

  for (int i=t; i<128; i+=256) scl[i] = g_chs[p0+i];
  __syncthreads();

  Frag F;
  gemm_core(smem_u32(smem), p0, g_h2_h, g_h2_l, CF, ch0, g_w4_h, g_w4_l, 0, CF/KC, F);

  float* Sv = (float*)smem;    // reuse staging
  const int wm = (wid & 1)*64, wn = (wid >> 1)*32;
  const int r0 = lane >> 2, cp = (lane & 3)*2;
  #pragma unroll
  for (int mi=0;mi<4;mi++){
    int pa = wm + mi*16 + r0;
    #pragma unroll
    for (int ni=0;ni<4;ni++){
      int chl = wn + ni*8 + cp;
      int ch  = ch0 + chl;
      float b0 = b4[ch], b1 = b4[ch+1];
      *(float2*)&Sv[(size_t)pa*SVSTR + chl] =
          make_float2(F.acc[mi][ni][0] + b0, F.acc[mi][ni][1] + b1);
      *(float2*)&Sv[(size_t)(pa+8)*SVSTR + chl] =
          make_float2(F.acc[mi][ni][2] + b0, F.acc[mi][ni][3] + b1);
    }
  }
  __syncthreads();

  {
    const int ch = t & 127, half = t >> 7;
    int r = half*64;
    int cprev = scl[r];
    float run = __int_as_float(0xff800000);
    unsigned* omb = &g_om[(size_t)bb*NCLST*CO + ch0 + ch];
    for (int i=0;i<64;i++,r++){
      int c = scl[r];
      if (c != cprev){
        atomicMax(&omb[(size_t)cprev*CO], enc(run));
        run = __int_as_float(0xff800000);
        cprev = c;
      }
      run = fmaxf(run, Sv[(size_t)r*SVSTR + ch]);
    }
    atomicMax(&omb[(size_t)cprev*CO], enc(run));
  }
}

__global__ void k_final(float* __restrict__ out){
  int i = blockIdx.x*blockDim.x + threadIdx.x;
  if (i < NFG*CO) out[i] = dec(g_om[i]);
}

// =====================================================================
extern "C" void kernel_launch(void* const* d_in, const int* in_sizes, int n_in,
                              void* d_out, int out_size)
{
  const float* xyz    = (const float*)d_in[0];
  const int*   choice = (const int*)  d_in[1];
  const float* w1  = (const float*)d_in[2];
  const float* b1  = (const float*)d_in[3];
  const float* g1  = (const float*)d_in[4];
  const float* bb1 = (const float*)d_in[5];
  const float* m1  = (const float*)d_in[6];
  const float* v1  = (const float*)d_in[7];
  const float* w2  = (const float*)d_in[8];
  const float* b2  = (const float*)d_in[9];
  const float* w3  = (const float*)d_in[10];
  const float* b3  = (const float*)d_in[11];
  const float* g2  = (const float*)d_in[12];
  const float* bb2 = (const float*)d_in[13];
  const float* m2  = (const float*)d_in[14];
  const float* v2  = (const float*)d_in[15];
  const float* w4  = (const float*)d_in[16];
  const float* b4  = (const float*)d_in[17];

  size_t smem1 = SVB;                      // 66560 (staging 40960 fits inside)
  size_t smemg = 2*BUFB;                   // 81920 (Sv 66560 fits inside)
  cudaFuncSetAttribute(k_stage1, cudaFuncAttributeMaxDynamicSharedMemorySize, (int)smem1);
  cudaFuncSetAttribute(k_gemmC,  cudaFuncAttributeMaxDynamicSharedMemorySize, (int)smemg);
  cudaFuncSetAttribute(k_gemm2,  cudaFuncAttributeMaxDynamicSharedMemorySize, (int)smemg);
  cudaFuncSetAttribute(k_gemm3,  cudaFuncAttributeMaxDynamicSharedMemorySize, (int)smemg);

  int ntot  = NFG*CO;
  int nprep = CF*CF + CO*CF + C2*C1 + CF + C1;

  k_init    <<<(ntot+255)/256, 256>>>();
  k_sort    <<<BATCH, 256>>>(choice);
  k_prep    <<<(nprep+255)/256, 256>>>(w1,b1,g1,bb1,m1,v1,w2, w3,w4,b3,g2,bb2,m2,v2);
  {
    dim3 g1d(PTOT/128, C2/128);   // (2048, 2)
    k_stage1<<<g1d, 256, smem1>>>(xyz, b2);
  }
  k_fg_split<<<(NFG*C2+255)/256, 256>>>();
  {
    dim3 gcd(NFG/128, CF/128);    // (16, 4)
    k_gemmC<<<gcd, 256, smemg>>>();
    dim3 g2d(PTOT/128, CF/128);   // (2048, 4)
    k_gemm2<<<g2d, 256, smemg>>>();
    dim3 g3d(PTOT/128, CO/128);   // (2048, 3)
    k_gemm3<<<g3d, 256, smemg>>>(b4);
  }
  k_final   <<<(ntot+255)/256, 256>>>((float*)d_out);
}